// round 3
// baseline (speedup 1.0000x reference)
#include <cuda_runtime.h>
#include <math.h>

#define B_SZ 512
#define T_SZ 512
#define IN_SZ 128
#define H_SZ 256
#define NB   128   // persistent blocks (<= 148 SMs: single wave, barrier-safe)

// ---------------- scratch (static device globals; no allocation) ----------------
__device__ float g_h0[2][B_SZ * H_SZ];
__device__ float g_h1[2][B_SZ * H_SZ];
__device__ float g_o0[B_SZ * 256];
__device__ float g_o1[B_SZ * 256];
__device__ float g_z [B_SZ * 64];

// grid barrier state (monotonic across replays; zero-initialized at load)
__device__ unsigned g_bar_count;
__device__ volatile unsigned g_bar_phase;

__device__ __forceinline__ float sigmoidf_(float x) { return 1.f / (1.f + expf(-x)); }

// Monotonic sense-reversing grid barrier. Barrier #n releases when the global
// arrive counter reaches 128*n — no counter reset, so no reset race, and state
// is consistent across graph replays (phase is re-read at kernel entry).
__device__ __forceinline__ void grid_bar(unsigned& phase) {
    __syncthreads();
    if (threadIdx.x == 0) {
        __threadfence();
        unsigned prev = phase;
        if (atomicAdd(&g_bar_count, 1u) == prev * (unsigned)NB + (NB - 1)) {
            __threadfence();
            g_bar_phase = prev + 1u;
        } else {
            while (g_bar_phase == prev) { __nanosleep(64); }
        }
        __threadfence();
    }
    __syncthreads();
    phase += 1u;
}

// ---------------- one GEMM phase of a GRU layer, double-buffered staging -------
// W: (768, K) row-major gate-major weights; X: SMEM tile (16, K).
// Each thread: 1 output unit (u_local) x 4 batch rows; 3 gate accumulators each.
template<int K>
__device__ __forceinline__ void phase_mm(
    const float* __restrict__ W, const float* __restrict__ X, float* ws,
    int tid, int us, int u_local, int bgrp,
    float* a0, float* a1, float* a2)
{
    float4 v[6];
    // prefetch chunk 0
    #pragma unroll
    for (int j = 0; j < 6; j++) {
        int idx = tid + j * 256;
        int c4 = idx & 7, row = idx >> 3;
        int g = row >> 6, uu = row & 63;
        v[j] = *(const float4*)(W + (long)(g * 256 + us * 64 + uu) * K + c4 * 4);
    }
    #pragma unroll
    for (int j = 0; j < 6; j++) {
        int idx = tid + j * 256;
        int c4 = idx & 7, row = idx >> 3;
        int g = row >> 6, uu = row & 63;
        *(float4*)(ws + (g * 64 + uu) * 36 + c4 * 4) = v[j];
    }
    __syncthreads();

    int cur = 0;
    for (int kc = 0; kc < K; kc += 32) {
        const bool more = (kc + 32 < K);
        if (more) {  // prefetch next chunk from global while computing current
            #pragma unroll
            for (int j = 0; j < 6; j++) {
                int idx = tid + j * 256;
                int c4 = idx & 7, row = idx >> 3;
                int g = row >> 6, uu = row & 63;
                v[j] = *(const float4*)(W + (long)(g * 256 + us * 64 + uu) * K
                                          + kc + 32 + c4 * 4);
            }
        }
        const float* wb = ws + cur * 6912;
        #pragma unroll
        for (int k = 0; k < 32; k += 4) {
            float4 w0 = *(const float4*)(wb + u_local * 36 + k);
            float4 w1 = *(const float4*)(wb + (64 + u_local) * 36 + k);
            float4 w2 = *(const float4*)(wb + (128 + u_local) * 36 + k);
            #pragma unroll
            for (int b = 0; b < 4; b++) {
                const float4 xv = *(const float4*)(X + (bgrp * 4 + b) * K + kc + k);
                a0[b] += xv.x * w0.x + xv.y * w0.y + xv.z * w0.z + xv.w * w0.w;
                a1[b] += xv.x * w1.x + xv.y * w1.y + xv.z * w1.z + xv.w * w1.w;
                a2[b] += xv.x * w2.x + xv.y * w2.y + xv.z * w2.z + xv.w * w2.w;
            }
        }
        if (more) {
            float* wn = ws + (cur ^ 1) * 6912;
            #pragma unroll
            for (int j = 0; j < 6; j++) {
                int idx = tid + j * 256;
                int c4 = idx & 7, row = idx >> 3;
                int g = row >> 6, uu = row & 63;
                *(float4*)(wn + (g * 64 + uu) * 36 + c4 * 4) = v[j];
            }
            __syncthreads();
            cur ^= 1;
        }
    }
}

// ---------------- one GRU layer for one timestep ----------------
template<int K1>
__device__ void gru_layer(
    const float* __restrict__ in, long in_stride,
    const float* __restrict__ Wih, const float* __restrict__ Whh,
    float br, float bz, float bn, float bh,
    const float* __restrict__ h_in, float* __restrict__ h_out,
    float* xs, float* hs, float* ws,
    int tid, int us, int u_local, int u, int bgrp, int b0)
{
    // input tile (16 x K1)
    for (int i = tid; i < 16 * K1 / 4; i += 256) {
        int bb = i / (K1 / 4), k4 = i % (K1 / 4);
        ((float4*)xs)[i] = *(const float4*)(in + (long)(b0 + bb) * in_stride + k4 * 4);
    }
    // hidden tile (16 x 256)
    for (int i = tid; i < 1024; i += 256) {
        int bb = i >> 6, k4 = i & 63;
        ((float4*)hs)[i] = *(const float4*)(h_in + (b0 + bb) * 256 + k4 * 4);
    }

    float ar[4], az[4], an[4], ah[4];
    #pragma unroll
    for (int b = 0; b < 4; b++) { ar[b] = br; az[b] = bz; an[b] = bn; ah[b] = bh; }

    phase_mm<K1 >(Wih, xs, ws, tid, us, u_local, bgrp, ar, az, an);
    phase_mm<256>(Whh, hs, ws, tid, us, u_local, bgrp, ar, az, ah);

    #pragma unroll
    for (int b = 0; b < 4; b++) {
        int bb = bgrp * 4 + b;
        float r  = sigmoidf_(ar[b]);
        float z  = sigmoidf_(az[b]);
        float n  = tanhf(an[b] + r * ah[b]);
        float hp = hs[bb * 256 + u];
        h_out[(long)(b0 + bb) * 256 + u] = (1.f - z) * n + z * hp;
    }
}

// ---------------- persistent GRU scan: both layers, all 512 steps ----------------
__global__ void __launch_bounds__(256) gru_persistent(
    const float* __restrict__ x,
    const float* __restrict__ W0i, const float* __restrict__ W0h,
    const float* __restrict__ b0i, const float* __restrict__ b0h,
    const float* __restrict__ W1i, const float* __restrict__ W1h,
    const float* __restrict__ b1i, const float* __restrict__ b1h)
{
    extern __shared__ float sm[];
    float* xs = sm;            // 16*256
    float* hs = sm + 4096;     // 16*256
    float* ws = sm + 8192;     // 2 * 3*64*36

    const int tid     = threadIdx.x;
    const int bg      = blockIdx.x >> 2;
    const int us      = blockIdx.x & 3;
    const int u_local = tid & 63;
    const int u       = us * 64 + u_local;
    const int bgrp    = tid >> 6;
    const int b0      = bg * 16;

    __shared__ unsigned s_ph;
    if (tid == 0) s_ph = g_bar_phase;

    // zero initial hidden states (buffer 0): 4 floats per thread per array
    {
        int base = blockIdx.x * 1024 + tid * 4;
        float4 z = make_float4(0.f, 0.f, 0.f, 0.f);
        *(float4*)&g_h0[0][base] = z;
        *(float4*)&g_h1[0][base] = z;
    }
    __syncthreads();
    unsigned phase = s_ph;
    grid_bar(phase);  // zeros visible grid-wide

    // per-layer bias terms (constant over steps)
    const float br0 = b0i[u]       + b0h[u];
    const float bz0 = b0i[256 + u] + b0h[256 + u];
    const float bn0 = b0i[512 + u];
    const float bh0 = b0h[512 + u];
    const float br1 = b1i[u]       + b1h[u];
    const float bz1 = b1i[256 + u] + b1h[256 + u];
    const float bn1 = b1i[512 + u];
    const float bh1 = b1h[512 + u];

    const long HB = (long)B_SZ * H_SZ;
    for (int t = 0; t < T_SZ; t++) {
        const int r = t & 1, w = r ^ 1;
        gru_layer<128>(x + (long)t * IN_SZ, (long)T_SZ * IN_SZ,
                       W0i, W0h, br0, bz0, bn0, bh0,
                       &g_h0[0][0] + r * HB, &g_h0[0][0] + w * HB,
                       xs, hs, ws, tid, us, u_local, u, bgrp, b0);
        grid_bar(phase);
        gru_layer<256>(&g_h0[0][0] + w * HB, 256L,
                       W1i, W1h, br1, bz1, bn1, bh1,
                       &g_h1[0][0] + r * HB, &g_h1[0][0] + w * HB,
                       xs, hs, ws, tid, us, u_local, u, bgrp, b0);
        grid_bar(phase);
    }
    // final h1 (t=511 odd -> w=0) lives in g_h1[0]
}

// ---------------- single-step LSTM pair (h0 = c0 = 0, f-gate dead) ----------
__global__ void __launch_bounds__(128) lstm_head_kernel(
    const float* __restrict__ s,
    const float* __restrict__ Wf, const float* __restrict__ bif, const float* __restrict__ bhf,
    const float* __restrict__ Wr, const float* __restrict__ bir, const float* __restrict__ bhr,
    float* __restrict__ out)
{
    __shared__ float ss[256];
    const int b = blockIdx.x, j = threadIdx.x;
    for (int i = j; i < 256; i += 128) ss[i] = s[b * 256 + i];
    __syncthreads();

    #pragma unroll
    for (int head = 0; head < 2; head++) {
        const float* W  = head ? Wr  : Wf;
        const float* bi = head ? bir : bif;
        const float* bh = head ? bhr : bhf;
        float di  = bi[j]       + bh[j];
        float dg  = bi[256 + j] + bh[256 + j];
        float doo = bi[384 + j] + bh[384 + j];
        const float* Wi = W + (long)j * 256;
        const float* Wg = W + (long)(256 + j) * 256;
        const float* Wo = W + (long)(384 + j) * 256;
        for (int k = 0; k < 256; k += 4) {
            float4 sv = *(const float4*)&ss[k];
            float4 wi = *(const float4*)(Wi + k);
            float4 wg = *(const float4*)(Wg + k);
            float4 wo = *(const float4*)(Wo + k);
            di  += sv.x * wi.x + sv.y * wi.y + sv.z * wi.z + sv.w * wi.w;
            dg  += sv.x * wg.x + sv.y * wg.y + sv.z * wg.z + sv.w * wg.w;
            doo += sv.x * wo.x + sv.y * wo.y + sv.z * wo.z + sv.w * wo.w;
        }
        float c = sigmoidf_(di) * tanhf(dg);
        out[b * 256 + head * 128 + j] = sigmoidf_(doo) * tanhf(c);
    }
}

// ---------------- KAN: cubic B-spline basis (GRID=5, ORDER=3 -> 8 bases) ----------
__device__ __forceinline__ void bspl8(float x, float* bv) {
    const float h = 0.4f;
    float p[12];
    #pragma unroll
    for (int m = 0; m < 12; m++) p[m] = (float)(m - 3) * h - 1.0f;
    float b[11];
    #pragma unroll
    for (int j = 0; j < 11; j++) b[j] = (x >= p[j] && x < p[j + 1]) ? 1.f : 0.f;
    #pragma unroll
    for (int k = 1; k <= 3; k++) {
        #pragma unroll
        for (int j = 0; j < 11 - k; j++) {
            b[j] = (x - p[j]) / (p[j + k] - p[j]) * b[j]
                 + (p[j + k + 1] - x) / (p[j + k + 1] - p[j + 1]) * b[j + 1];
        }
    }
    #pragma unroll
    for (int j = 0; j < 8; j++) bv[j] = b[j];
}

template<int NIN, int NOUT, int NT>
__global__ void __launch_bounds__(NT) kan_kernel(
    const float* __restrict__ in,
    const float* __restrict__ base_w,
    const float* __restrict__ spline_w,
    const float* __restrict__ scaler,
    float* __restrict__ out)
{
    __shared__ float silu_s[NIN];
    __shared__ float bsp_s[NIN][8];
    const int b = blockIdx.x;
    for (int i = threadIdx.x; i < NIN; i += NT) {
        float x = in[b * NIN + i];
        silu_s[i] = x * (1.f / (1.f + expf(-x)));
        bspl8(x, &bsp_s[i][0]);
    }
    __syncthreads();
    for (int o = threadIdx.x; o < NOUT; o += NT) {
        float acc = 0.f;
        for (int i = 0; i < NIN; i++) {
            acc += silu_s[i] * base_w[o * NIN + i];
            const float* sp = spline_w + ((long)o * NIN + i) * 8;
            float s8 = 0.f;
            #pragma unroll
            for (int k = 0; k < 8; k++) s8 += bsp_s[i][k] * sp[k];
            acc += scaler[o * NIN + i] * s8;
        }
        out[b * NOUT + o] = acc;
    }
}

// ---------------- launch ----------------
extern "C" void kernel_launch(void* const* d_in, const int* in_sizes, int n_in,
                              void* d_out, int out_size) {
    const float* x        = (const float*)d_in[0];
    const float* g0_wih   = (const float*)d_in[1];
    const float* g0_whh   = (const float*)d_in[2];
    const float* g0_bih   = (const float*)d_in[3];
    const float* g0_bhh   = (const float*)d_in[4];
    const float* g1_wih   = (const float*)d_in[5];
    const float* g1_whh   = (const float*)d_in[6];
    const float* g1_bih   = (const float*)d_in[7];
    const float* g1_bhh   = (const float*)d_in[8];
    const float* lw_ih0   = (const float*)d_in[9];
    const float* lb_ih0   = (const float*)d_in[11];
    const float* lb_hh0   = (const float*)d_in[12];
    const float* lw_ih0r  = (const float*)d_in[13];
    const float* lb_ih0r  = (const float*)d_in[15];
    const float* lb_hh0r  = (const float*)d_in[16];
    const float* lw_ih1   = (const float*)d_in[17];
    const float* lb_ih1   = (const float*)d_in[19];
    const float* lb_hh1   = (const float*)d_in[20];
    const float* lw_ih1r  = (const float*)d_in[21];
    const float* lb_ih1r  = (const float*)d_in[23];
    const float* lb_hh1r  = (const float*)d_in[24];
    const float* kan1_base   = (const float*)d_in[25];
    const float* kan1_spline = (const float*)d_in[26];
    const float* kan1_scaler = (const float*)d_in[27];
    const float* kan2_base   = (const float*)d_in[28];
    const float* kan2_spline = (const float*)d_in[29];
    const float* kan2_scaler = (const float*)d_in[30];

    float *h1, *o0, *o1, *zz;
    cudaGetSymbolAddress((void**)&h1, g_h1);
    cudaGetSymbolAddress((void**)&o0, g_o0);
    cudaGetSymbolAddress((void**)&o1, g_o1);
    cudaGetSymbolAddress((void**)&zz, g_z);

    const int smem = (4096 + 4096 + 2 * 6912) * 4;  // 88064 B
    cudaFuncSetAttribute(gru_persistent, cudaFuncAttributeMaxDynamicSharedMemorySize, smem);

    gru_persistent<<<NB, 256, smem>>>(x,
                                      g0_wih, g0_whh, g0_bih, g0_bhh,
                                      g1_wih, g1_whh, g1_bih, g1_bhh);

    lstm_head_kernel<<<512, 128>>>(h1, lw_ih0, lb_ih0, lb_hh0,
                                   lw_ih0r, lb_ih0r, lb_hh0r, o0);
    lstm_head_kernel<<<512, 128>>>(o0, lw_ih1, lb_ih1, lb_hh1,
                                   lw_ih1r, lb_ih1r, lb_hh1r, o1);
    kan_kernel<256, 64, 64><<<512, 64>>>(o1, kan1_base, kan1_spline, kan1_scaler, zz);
    kan_kernel<64, 10, 32><<<512, 32>>>(zz, kan2_base, kan2_spline, kan2_scaler, (float*)d_out);
}